// round 8
// baseline (speedup 1.0000x reference)
#include <cuda_runtime.h>
#include <cuda_bf16.h>
#include <cstdint>

// Problem shape (fixed by reference)
#define Bq   4
#define Sq   1024
#define Hq   32
#define Dq   128
#define SMAX 2048

// Element-count layout (common promoted dtype = float32):
//   [new_ck | new_cks | new_cv | new_cvs]
static constexpr long long CK_ELEMS = (long long)SMAX * Hq * Bq * Dq;  // 33,554,432
static constexpr long long SC_ELEMS = (long long)SMAX * Hq * Bq;       //    262,144
static constexpr long long OFF_CK  = 0;
static constexpr long long OFF_CKS = OFF_CK  + CK_ELEMS;               // 33,554,432
static constexpr long long OFF_CV  = OFF_CKS + SC_ELEMS;               // 33,816,576
static constexpr long long OFF_CVS = OFF_CV  + CK_ELEMS;               // 67,371,008
static constexpr long long TOT_ELEMS = OFF_CVS + SC_ELEMS;             // 67,633,152

// Native-dtype byte-concat layout (fallback if out_size says so):
static constexpr long long BOFF_CK  = 0;
static constexpr long long BOFF_CKS = BOFF_CK  + CK_ELEMS;             // bytes
static constexpr long long BOFF_CV  = BOFF_CKS + SC_ELEMS * 2;
static constexpr long long BOFF_CVS = BOFF_CV  + CK_ELEMS;
static constexpr long long TOT_BYTES = BOFF_CVS + SC_ELEMS * 2;        // 68,157,440

// ===========================================================================
// Shared quantization math: IEEE-rn boundary ops + SATURATING int8 convert
// (XLA convert_element_type saturates out-of-range float->int; the row-max
//  element rounds to +/-128 in ~half the rows, so +128 must clamp to 127.)
// ===========================================================================
__device__ __forceinline__ void quant_row(
    const float4 v, float& m, int& q0, int& q1, int& q2, int& q3)
{
    m = fmaxf(fmaxf(fabsf(v.x), fabsf(v.y)), fmaxf(fabsf(v.z), fabsf(v.w)));
    #pragma unroll
    for (int o = 16; o > 0; o >>= 1)
        m = fmaxf(m, __shfl_xor_sync(0xffffffffu, m, o));

    const float t = __fdiv_rn(127.5f, m);   // IEEE rn: 127/128 decision must match XLA
    q0 = max(-128, min(127, (int)rintf(__fmul_rn(v.x, t))));
    q1 = max(-128, min(127, (int)rintf(__fmul_rn(v.y, t))));
    q2 = max(-128, min(127, (int)rintf(__fmul_rn(v.z, t))));
    q3 = max(-128, min(127, (int)rintf(__fmul_rn(v.w, t))));
}

// ===========================================================================
// MODE A: common float32 output (confirmed by R7 evidence)
// ===========================================================================
__global__ void __launch_bounds__(256) quant_f32(
    const float* __restrict__ key, const float* __restrict__ val,
    float* __restrict__ out)
{
    const int lane   = threadIdx.x & 31;
    const int warpId = blockIdx.x * (blockDim.x >> 5) + (threadIdx.x >> 5);
    const int ROWS   = Bq * Sq * Hq;                 // 131072 rows per tensor
    const bool isV   = warpId >= ROWS;
    const int  r     = isV ? (warpId - ROWS) : warpId;

    const float4 v = reinterpret_cast<const float4*>(
        (isV ? val : key) + (long long)r * Dq)[lane];

    float m; int q0, q1, q2, q3;
    quant_row(v, m, q0, q1, q2, q3);

    const int b  = r >> 15;          // / (S*H)
    const int sh = r & 32767;        // s*H + h

    const float4 o = make_float4((float)q0, (float)q1, (float)q2, (float)q3);
    const long long obase = (isV ? OFF_CV : OFF_CK) + (((long long)sh * Bq + b) << 7);
    reinterpret_cast<float4*>(out + obase)[lane] = o;

    if (lane == 0)   // compared value is the reference's bf16 round-trip of m
        out[(isV ? OFF_CVS : OFF_CKS) + (long long)sh * Bq + b] =
            __bfloat162float(__float2bfloat16(m));
}

__global__ void __launch_bounds__(256) tail_f32(
    const signed char* __restrict__ ck, const signed char* __restrict__ cv,
    float* __restrict__ out)
{
    const long long HALF = (long long)Sq * Hq * Bq * Dq;   // 16,777,216
    const long long NTH  = HALF >> 3;                      // threads per tensor
    const long long tid  = (long long)blockIdx.x * blockDim.x + threadIdx.x;
    const bool isV = tid >= NTH;
    const long long i = ((isV ? tid - NTH : tid) << 3) + HALF;

    const uint2 raw = *reinterpret_cast<const uint2*>((isV ? cv : ck) + i);
    float4 a, bq;
    a.x  = (float)(signed char)(raw.x         & 0xFF);
    a.y  = (float)(signed char)((raw.x >> 8)  & 0xFF);
    a.z  = (float)(signed char)((raw.x >> 16) & 0xFF);
    a.w  = (float)(signed char)((raw.x >> 24) & 0xFF);
    bq.x = (float)(signed char)(raw.y         & 0xFF);
    bq.y = (float)(signed char)((raw.y >> 8)  & 0xFF);
    bq.z = (float)(signed char)((raw.y >> 16) & 0xFF);
    bq.w = (float)(signed char)((raw.y >> 24) & 0xFF);

    float* dst = out + (isV ? OFF_CV : OFF_CK) + i;
    reinterpret_cast<float4*>(dst)[0] = a;
    reinterpret_cast<float4*>(dst)[1] = bq;
}

__global__ void __launch_bounds__(256) scale_tail_f32(
    const __nv_bfloat16* __restrict__ cks, const __nv_bfloat16* __restrict__ cvs,
    float* __restrict__ out)
{
    const long long NEWS = (long long)Sq * Hq * Bq;  // 131,072
    const long long NV   = NEWS >> 2;                // 4 elems/thread
    const long long tid  = (long long)blockIdx.x * blockDim.x + threadIdx.x;
    const bool isV = tid >= NV;
    const long long i = ((isV ? tid - NV : tid) << 2) + NEWS;

    const uint2 raw = *reinterpret_cast<const uint2*>((isV ? cvs : cks) + i);
    float4 o;
    o.x = __bfloat162float(__ushort_as_bfloat16((unsigned short)(raw.x & 0xFFFF)));
    o.y = __bfloat162float(__ushort_as_bfloat16((unsigned short)(raw.x >> 16)));
    o.z = __bfloat162float(__ushort_as_bfloat16((unsigned short)(raw.y & 0xFFFF)));
    o.w = __bfloat162float(__ushort_as_bfloat16((unsigned short)(raw.y >> 16)));
    *reinterpret_cast<float4*>(out + (isV ? OFF_CVS : OFF_CKS) + i) = o;
}

// ===========================================================================
// MODE B: native-dtype byte concat (fallback, out_size == 68,157,440)
// ===========================================================================
__global__ void __launch_bounds__(256) quant_native(
    const float* __restrict__ key, const float* __restrict__ val,
    unsigned char* __restrict__ outb)
{
    const int lane   = threadIdx.x & 31;
    const int warpId = blockIdx.x * (blockDim.x >> 5) + (threadIdx.x >> 5);
    const int ROWS   = Bq * Sq * Hq;
    const bool isV   = warpId >= ROWS;
    const int  r     = isV ? (warpId - ROWS) : warpId;

    const float4 v = reinterpret_cast<const float4*>(
        (isV ? val : key) + (long long)r * Dq)[lane];

    float m; int q0, q1, q2, q3;
    quant_row(v, m, q0, q1, q2, q3);

    const int b  = r >> 15;
    const int sh = r & 32767;

    const unsigned pk = (unsigned)(unsigned char)(signed char)q0
                      | ((unsigned)(unsigned char)(signed char)q1 << 8)
                      | ((unsigned)(unsigned char)(signed char)q2 << 16)
                      | ((unsigned)(unsigned char)(signed char)q3 << 24);
    const long long obase = (isV ? BOFF_CV : BOFF_CK) + (((long long)sh * Bq + b) << 7);
    reinterpret_cast<unsigned*>(outb + obase)[lane] = pk;

    if (lane == 0)
        *reinterpret_cast<__nv_bfloat16*>(
            outb + (isV ? BOFF_CVS : BOFF_CKS) + 2 * ((long long)sh * Bq + b)) =
            __float2bfloat16(m);
}

__global__ void __launch_bounds__(256) tail_native(
    const signed char* __restrict__ ck, const signed char* __restrict__ cv,
    const __nv_bfloat16* __restrict__ cks, const __nv_bfloat16* __restrict__ cvs,
    unsigned char* __restrict__ outb)
{
    const long long HALF = (long long)Sq * Hq * Bq * Dq;   // bytes
    const long long NTH  = HALF >> 4;
    const long long tid  = (long long)blockIdx.x * blockDim.x + threadIdx.x;

    if (tid < 2 * NTH) {
        const bool isV = tid >= NTH;
        const long long i = ((isV ? tid - NTH : tid) << 4) + HALF;
        const uint4 v = *reinterpret_cast<const uint4*>((isV ? cv : ck) + i);
        *reinterpret_cast<uint4*>(outb + (isV ? BOFF_CV : BOFF_CK) + i) = v;
    } else {
        const long long NEWSB = (long long)Sq * Hq * Bq * 2;
        const long long NSV   = NEWSB >> 4;
        const long long t2 = tid - 2 * NTH;
        if (t2 < 2 * NSV) {
            const bool isV = t2 >= NSV;
            const long long i = ((isV ? t2 - NSV : t2) << 4) + NEWSB;
            const uint4 v = *reinterpret_cast<const uint4*>(
                reinterpret_cast<const unsigned char*>(isV ? cvs : cks) + i);
            *reinterpret_cast<uint4*>(outb + (isV ? BOFF_CVS : BOFF_CKS) + i) = v;
        }
    }
}

// ===========================================================================
// Launch. Inputs: key f32, value f32, cached_key i8, cached_value i8,
//                 cached_key_scale bf16, cached_value_scale bf16
// ===========================================================================
extern "C" void kernel_launch(void* const* d_in, const int* in_sizes, int n_in,
                              void* d_out, int out_size)
{
    const float*         key = (const float*)d_in[0];
    const float*         val = (const float*)d_in[1];
    const signed char*   ck  = (const signed char*)d_in[2];
    const signed char*   cv  = (const signed char*)d_in[3];
    const __nv_bfloat16* cks = (const __nv_bfloat16*)d_in[4];
    const __nv_bfloat16* cvs = (const __nv_bfloat16*)d_in[5];

    if ((long long)out_size == TOT_BYTES) {
        unsigned char* outb = (unsigned char*)d_out;
        quant_native<<<32768, 256>>>(key, val, outb);
        tail_native<<<8320, 256>>>(ck, cv, cks, cvs, outb);
    } else {
        float* out = (float*)d_out;
        quant_f32<<<32768, 256>>>(key, val, out);
        tail_f32<<<16384, 256>>>(ck, cv, out);
        scale_tail_f32<<<256, 256>>>(cks, cvs, out);
    }
}

// round 10
// speedup vs baseline: 1.0717x; 1.0717x over previous
#include <cuda_runtime.h>
#include <cuda_bf16.h>
#include <cstdint>

// Problem shape (fixed by reference)
#define Bq   4
#define Sq   1024
#define Hq   32
#define Dq   128
#define SMAX 2048

// Flattened float32 output layout (confirmed R8): [new_ck | new_cks | new_cv | new_cvs]
static constexpr long long CK_ELEMS = (long long)SMAX * Hq * Bq * Dq;  // 33,554,432
static constexpr long long SC_ELEMS = (long long)SMAX * Hq * Bq;       //    262,144
static constexpr long long OFF_CK  = 0;
static constexpr long long OFF_CKS = OFF_CK  + CK_ELEMS;               // 33,554,432
static constexpr long long OFF_CV  = OFF_CKS + SC_ELEMS;               // 33,816,576
static constexpr long long OFF_CVS = OFF_CV  + CK_ELEMS;               // 67,371,008

// Fused-grid partition (256 threads/block everywhere)
static constexpr int QUANT_BLOCKS = 32768;  // 2*131072 rows, 1 warp/row, 8 warps/blk
static constexpr int TAIL_BLOCKS  = 16384;  // 2*2,097,152 threads, 8 int8 -> 8 f32 each
static constexpr int SCALE_BLOCKS = 256;    // 2*32,768 threads, 4 bf16 -> 4 f32 each
static constexpr int TOTAL_BLOCKS = QUANT_BLOCKS + TAIL_BLOCKS + SCALE_BLOCKS;

__global__ void __launch_bounds__(256) kv_fused(
    const float*         __restrict__ key,
    const float*         __restrict__ val,
    const signed char*   __restrict__ ck,
    const signed char*   __restrict__ cv,
    const __nv_bfloat16* __restrict__ cks,
    const __nv_bfloat16* __restrict__ cvs,
    float*               __restrict__ out)
{
    const int bid = blockIdx.x;

    if (bid < QUANT_BLOCKS) {
        // ------------------------------------------------------------------
        // Quantize + transpose-scatter. One warp per (b,s,h) row.
        // ------------------------------------------------------------------
        const int lane   = threadIdx.x & 31;
        const int warpId = bid * 8 + (threadIdx.x >> 5);
        const int ROWS   = Bq * Sq * Hq;             // 131072 rows per tensor
        const bool isV   = warpId >= ROWS;
        const int  r     = isV ? (warpId - ROWS) : warpId;

        const float4 v = reinterpret_cast<const float4*>(
            (isV ? val : key) + (long long)r * Dq)[lane];

        // abs-max via single REDUX: IEEE order == unsigned order for abs values
        const float lm = fmaxf(fmaxf(fabsf(v.x), fabsf(v.y)),
                               fmaxf(fabsf(v.z), fabsf(v.w)));
        const float m = __uint_as_float(
            __reduce_max_sync(0xffffffffu, __float_as_uint(lm)));

        // IEEE-rn div/mul: the row-max element lands at 127.5 +/- ulp and the
        // 127-vs-128 rounding decision must match XLA bit-exactly.
        const float t = __fdiv_rn(127.5f, m);

        // rint + saturate entirely in float (output dtype is f32; the int
        // round-trip was pure instruction waste). Exact on integer values.
        float4 o;
        o.x = fminf(fmaxf(rintf(__fmul_rn(v.x, t)), -128.0f), 127.0f);
        o.y = fminf(fmaxf(rintf(__fmul_rn(v.y, t)), -128.0f), 127.0f);
        o.z = fminf(fmaxf(rintf(__fmul_rn(v.z, t)), -128.0f), 127.0f);
        o.w = fminf(fmaxf(rintf(__fmul_rn(v.w, t)), -128.0f), 127.0f);

        const int b  = r >> 15;          // / (S*H)
        const int sh = r & 32767;        // s*H + h

        const long long obase =
            (isV ? OFF_CV : OFF_CK) + (((long long)sh * Bq + b) << 7);
        reinterpret_cast<float4*>(out + obase)[lane] = o;

        if (lane == 0)   // reference's bf16 round-trip of the scale
            out[(isV ? OFF_CVS : OFF_CKS) + (long long)sh * Bq + b] =
                __bfloat162float(__float2bfloat16(m));
    }
    else if (bid < QUANT_BLOCKS + TAIL_BLOCKS) {
        // ------------------------------------------------------------------
        // Untouched cache tail (s in [1024,2048)): int8 -> f32 pass-through.
        // ------------------------------------------------------------------
        const long long HALF = (long long)Sq * Hq * Bq * Dq;   // 16,777,216
        const long long NTH  = HALF >> 3;                      // threads/tensor
        const long long tid  =
            (long long)(bid - QUANT_BLOCKS) * 256 + threadIdx.x;
        const bool isV = tid >= NTH;
        const long long i = ((isV ? tid - NTH : tid) << 3) + HALF;

        const uint2 raw = *reinterpret_cast<const uint2*>((isV ? cv : ck) + i);
        float4 a, bq;
        a.x  = (float)(signed char)(raw.x         & 0xFF);
        a.y  = (float)(signed char)((raw.x >> 8)  & 0xFF);
        a.z  = (float)(signed char)((raw.x >> 16) & 0xFF);
        a.w  = (float)(signed char)((raw.x >> 24) & 0xFF);
        bq.x = (float)(signed char)(raw.y         & 0xFF);
        bq.y = (float)(signed char)((raw.y >> 8)  & 0xFF);
        bq.z = (float)(signed char)((raw.y >> 16) & 0xFF);
        bq.w = (float)(signed char)((raw.y >> 24) & 0xFF);

        float* dst = out + (isV ? OFF_CV : OFF_CK) + i;
        reinterpret_cast<float4*>(dst)[0] = a;
        reinterpret_cast<float4*>(dst)[1] = bq;
    }
    else {
        // ------------------------------------------------------------------
        // Untouched scale tail: bf16 -> f32.
        // ------------------------------------------------------------------
        const long long NEWS = (long long)Sq * Hq * Bq;  // 131,072
        const long long NV   = NEWS >> 2;                // 4 elems/thread
        const long long tid  =
            (long long)(bid - QUANT_BLOCKS - TAIL_BLOCKS) * 256 + threadIdx.x;
        const bool isV = tid >= NV;
        const long long i = ((isV ? tid - NV : tid) << 2) + NEWS;

        const uint2 raw = *reinterpret_cast<const uint2*>((isV ? cvs : cks) + i);
        float4 o;
        o.x = __bfloat162float(__ushort_as_bfloat16((unsigned short)(raw.x & 0xFFFF)));
        o.y = __bfloat162float(__ushort_as_bfloat16((unsigned short)(raw.x >> 16)));
        o.z = __bfloat162float(__ushort_as_bfloat16((unsigned short)(raw.y & 0xFFFF)));
        o.w = __bfloat162float(__ushort_as_bfloat16((unsigned short)(raw.y >> 16)));
        *reinterpret_cast<float4*>(out + (isV ? OFF_CVS : OFF_CKS) + i) = o;
    }
}

// ===========================================================================
// Launch. Inputs: key f32, value f32, cached_key i8, cached_value i8,
//                 cached_key_scale bf16, cached_value_scale bf16
// ===========================================================================
extern "C" void kernel_launch(void* const* d_in, const int* in_sizes, int n_in,
                              void* d_out, int out_size)
{
    const float*         key = (const float*)d_in[0];
    const float*         val = (const float*)d_in[1];
    const signed char*   ck  = (const signed char*)d_in[2];
    const signed char*   cv  = (const signed char*)d_in[3];
    const __nv_bfloat16* cks = (const __nv_bfloat16*)d_in[4];
    const __nv_bfloat16* cvs = (const __nv_bfloat16*)d_in[5];
    float* out = (float*)d_out;

    kv_fused<<<TOTAL_BLOCKS, 256>>>(key, val, ck, cv, cks, cvs, out);
}

// round 11
// speedup vs baseline: 1.1259x; 1.0506x over previous
#include <cuda_runtime.h>
#include <cuda_bf16.h>
#include <cstdint>

// Problem shape (fixed by reference)
#define Bq   4
#define Sq   1024
#define Hq   32
#define Dq   128
#define SMAX 2048

// Flattened float32 output layout (confirmed R8): [new_ck | new_cks | new_cv | new_cvs]
static constexpr long long CK_ELEMS = (long long)SMAX * Hq * Bq * Dq;  // 33,554,432
static constexpr long long SC_ELEMS = (long long)SMAX * Hq * Bq;       //    262,144
static constexpr long long OFF_CK  = 0;
static constexpr long long OFF_CKS = OFF_CK  + CK_ELEMS;               // 33,554,432
static constexpr long long OFF_CV  = OFF_CKS + SC_ELEMS;               // 33,816,576
static constexpr long long OFF_CVS = OFF_CV  + CK_ELEMS;               // 67,371,008

// Grid partition: quant and tail roles interleaved 4:1 within every wave so the
// DRAM read/write mix stays balanced for the whole run (R10 ran all-quant waves
// then write-heavy all-tail waves).
static constexpr int QUANT_BLOCKS = 32768;  // 2*131072 rows, 1 warp/row, 8 warps/blk
static constexpr int TAIL_BLOCKS  = 8192;   // 2*1,048,576 threads, 16 int8 -> 64B out
static constexpr int MIX_BLOCKS   = QUANT_BLOCKS + TAIL_BLOCKS;  // 40960 (= 8192*5)
static constexpr int SCALE_BLOCKS = 256;    // 2*32,768 threads, 4 bf16 -> 4 f32 each
static constexpr int TOTAL_BLOCKS = MIX_BLOCKS + SCALE_BLOCKS;

__global__ void __launch_bounds__(256) kv_fused(
    const float*         __restrict__ key,
    const float*         __restrict__ val,
    const signed char*   __restrict__ ck,
    const signed char*   __restrict__ cv,
    const __nv_bfloat16* __restrict__ cks,
    const __nv_bfloat16* __restrict__ cvs,
    float*               __restrict__ out)
{
    const int bid = blockIdx.x;

    if (bid < MIX_BLOCKS) {
        const int g   = bid / 5;     // 8192 groups of (4 quant + 1 tail)
        const int rem = bid - g * 5;

        if (rem < 4) {
            // --------------------------------------------------------------
            // Quantize + transpose-scatter. One warp per (b,s,h) row.
            // --------------------------------------------------------------
            const int qbid   = g * 4 + rem;              // [0, 32768)
            const int lane   = threadIdx.x & 31;
            const int warpId = qbid * 8 + (threadIdx.x >> 5);
            const int ROWS   = Bq * Sq * Hq;             // 131072 rows / tensor
            const bool isV   = warpId >= ROWS;
            const int  r     = isV ? (warpId - ROWS) : warpId;

            const float4 v = __ldcs(reinterpret_cast<const float4*>(
                (isV ? val : key) + (long long)r * Dq) + lane);

            // abs-max via REDUX: IEEE order == unsigned order for abs values
            const float lm = fmaxf(fmaxf(fabsf(v.x), fabsf(v.y)),
                                   fmaxf(fabsf(v.z), fabsf(v.w)));
            const float m = __uint_as_float(
                __reduce_max_sync(0xffffffffu, __float_as_uint(lm)));

            // IEEE-rn div/mul: 127-vs-128 rounding decision must match XLA.
            const float t = __fdiv_rn(127.5f, m);

            // rint + saturate in float domain (exact on integers).
            float4 o;
            o.x = fminf(fmaxf(rintf(__fmul_rn(v.x, t)), -128.0f), 127.0f);
            o.y = fminf(fmaxf(rintf(__fmul_rn(v.y, t)), -128.0f), 127.0f);
            o.z = fminf(fmaxf(rintf(__fmul_rn(v.z, t)), -128.0f), 127.0f);
            o.w = fminf(fmaxf(rintf(__fmul_rn(v.w, t)), -128.0f), 127.0f);

            const int b  = r >> 15;          // / (S*H)
            const int sh = r & 32767;        // s*H + h

            const long long obase =
                (isV ? OFF_CV : OFF_CK) + (((long long)sh * Bq + b) << 7);
            __stcs(reinterpret_cast<float4*>(out + obase) + lane, o);

            if (lane == 0)   // reference's bf16 round-trip of the scale
                out[(isV ? OFF_CVS : OFF_CKS) + (long long)sh * Bq + b] =
                    __bfloat162float(__float2bfloat16(m));
        } else {
            // --------------------------------------------------------------
            // Untouched cache tail (s in [1024,2048)): int8 -> f32.
            // 16 int8 in (one uint4), 4x float4 out per thread.
            // --------------------------------------------------------------
            const long long HALF = (long long)Sq * Hq * Bq * Dq;  // 16,777,216
            const long long NTH  = HALF >> 4;                     // 1,048,576 /tensor
            const long long tid  = (long long)g * 256 + threadIdx.x;
            const bool isV = tid >= NTH;
            const long long i = ((isV ? tid - NTH : tid) << 4) + HALF;

            const uint4 raw =
                __ldcs(reinterpret_cast<const uint4*>((isV ? cv : ck) + i));
            float4* dst = reinterpret_cast<float4*>(
                out + (isV ? OFF_CV : OFF_CK) + i);

            const unsigned w[4] = {raw.x, raw.y, raw.z, raw.w};
            #pragma unroll
            for (int k = 0; k < 4; k++) {
                float4 f;
                f.x = (float)(signed char)( w[k]        & 0xFF);
                f.y = (float)(signed char)((w[k] >> 8)  & 0xFF);
                f.z = (float)(signed char)((w[k] >> 16) & 0xFF);
                f.w = (float)(signed char)((w[k] >> 24) & 0xFF);
                __stcs(dst + k, f);
            }
        }
    }
    else {
        // ------------------------------------------------------------------
        // Untouched scale tail: bf16 -> f32, 4 elems/thread.
        // ------------------------------------------------------------------
        const long long NEWS = (long long)Sq * Hq * Bq;  // 131,072
        const long long NV   = NEWS >> 2;
        const long long tid  = (long long)(bid - MIX_BLOCKS) * 256 + threadIdx.x;
        const bool isV = tid >= NV;
        const long long i = ((isV ? tid - NV : tid) << 2) + NEWS;

        const uint2 raw =
            __ldcs(reinterpret_cast<const uint2*>((isV ? cvs : cks) + i));
        float4 o;
        o.x = __bfloat162float(__ushort_as_bfloat16((unsigned short)(raw.x & 0xFFFF)));
        o.y = __bfloat162float(__ushort_as_bfloat16((unsigned short)(raw.x >> 16)));
        o.z = __bfloat162float(__ushort_as_bfloat16((unsigned short)(raw.y & 0xFFFF)));
        o.w = __bfloat162float(__ushort_as_bfloat16((unsigned short)(raw.y >> 16)));
        __stcs(reinterpret_cast<float4*>(out + (isV ? OFF_CVS : OFF_CKS) + i), o);
    }
}

// ===========================================================================
// Launch. Inputs: key f32, value f32, cached_key i8, cached_value i8,
//                 cached_key_scale bf16, cached_value_scale bf16
// ===========================================================================
extern "C" void kernel_launch(void* const* d_in, const int* in_sizes, int n_in,
                              void* d_out, int out_size)
{
    const float*         key = (const float*)d_in[0];
    const float*         val = (const float*)d_in[1];
    const signed char*   ck  = (const signed char*)d_in[2];
    const signed char*   cv  = (const signed char*)d_in[3];
    const __nv_bfloat16* cks = (const __nv_bfloat16*)d_in[4];
    const __nv_bfloat16* cvs = (const __nv_bfloat16*)d_in[5];
    float* out = (float*)d_out;

    kv_fused<<<TOTAL_BLOCKS, 256>>>(key, val, ck, cv, cks, cvs, out);
}